// round 6
// baseline (speedup 1.0000x reference)
#include <cuda_runtime.h>
#include <cuda_bf16.h>

#define FEAT 64
#define EPR 168             // edges per 16-lane group
#define ROWS_PER_BLOCK 16   // 256 threads / 16 lanes
#define THREADS 256
#define MAXG 32768          // max groups supported (E <= MAXG*EPR)

#define FLG_FULL       1    // whole chunk is a single run
#define FLG_OWNED_TAIL 2    // this group owns a boundary-crossing segment

// Scratch (allocation-free: __device__ globals). Rewritten every launch for
// every slot that K2 can read -> idempotent across graph replays.
__device__ float4 g_scratch_head[MAXG * 16];  // continuation partial per group
__device__ float4 g_scratch_tail[MAXG * 16];  // owner's tail partial per group
__device__ int    g_tail_id[MAXG];
__device__ unsigned char g_flags[MAXG];

// K1: weighted segment-sum over sorted segment_ids; plain stores only.
__global__ void __launch_bounds__(THREADS)
segsum_kernel(const float4* __restrict__ feats,   // [E,16] float4 view of [E,64]
              const float*  __restrict__ attn,    // [E]
              const int*    __restrict__ seg,     // [E] sorted
              float* __restrict__ out,            // [N,64] (written, never RMW)
              const float4* __restrict__ bias4,   // [16]
              int n_edges, int n_nodes) {
    int row  = blockIdx.x * ROWS_PER_BLOCK + (threadIdx.x >> 4);
    int lane = threadIdx.x & 15;

    int e0 = row * EPR;
    if (e0 >= n_edges) return;
    int e_end = e0 + EPR;
    if (e_end > n_edges) e_end = n_edges;

    float4 bia = __ldg(&bias4[lane]);
    float4 acc = make_float4(0.f, 0.f, 0.f, 0.f);
    int  cur   = __ldg(&seg[e0]);
    bool first = true;
    bool owned_head = (e0 == 0) || (__ldg(&seg[e0 - 1]) != cur);

    // leading empty nodes [0, seg[0]) — only the very first group
    if (e0 == 0) {
        for (int m = 0; m < cur; ++m)
            ((float4*)(out + (size_t)m * FEAT))[lane] = bia;
    }

    #pragma unroll 4
    for (int e = e0; e < e_end; ++e) {
        int   s = __ldg(&seg[e]);
        float a = __ldg(&attn[e]);
        float4 f = __ldg(&feats[(size_t)e * 16 + lane]);

        if (s != cur) {
            if (first && !owned_head) {
                // continuation of a segment owned by an earlier group
                g_scratch_head[(size_t)row * 16 + lane] = acc;
            } else {
                // run fully completed here and owned -> sole writer
                float4 v = make_float4(acc.x + bia.x, acc.y + bia.y,
                                       acc.z + bia.z, acc.w + bia.w);
                ((float4*)(out + (size_t)cur * FEAT))[lane] = v;
            }
            // empty nodes strictly between cur and s
            for (int m = cur + 1; m < s; ++m)
                ((float4*)(out + (size_t)m * FEAT))[lane] = bia;
            first = false;
            acc = make_float4(0.f, 0.f, 0.f, 0.f);
            cur = s;
        }
        acc.x = fmaf(a, f.x, acc.x);
        acc.y = fmaf(a, f.y, acc.y);
        acc.z = fmaf(a, f.z, acc.z);
        acc.w = fmaf(a, f.w, acc.w);
    }

    // tail flush
    bool has_next = (e_end < n_edges);
    int  next_s   = has_next ? __ldg(&seg[e_end]) : n_nodes;
    bool tail_shared = has_next && (next_s == cur);

    unsigned char flag = first ? FLG_FULL : 0;
    if (first && !owned_head) {
        // whole chunk is a continuation partial
        g_scratch_head[(size_t)row * 16 + lane] = acc;
    } else if (tail_shared) {
        // we own a segment that crosses into following chunks -> K2 finalizes
        g_scratch_tail[(size_t)row * 16 + lane] = acc;
        flag |= FLG_OWNED_TAIL;
    } else {
        float4 v = make_float4(acc.x + bia.x, acc.y + bia.y,
                               acc.z + bia.z, acc.w + bia.w);
        ((float4*)(out + (size_t)cur * FEAT))[lane] = v;
    }
    if (lane == 0) {
        g_flags[row]   = flag;
        g_tail_id[row] = cur;
    }

    // trailing empty nodes up to next chunk's first segment (or n_nodes)
    for (int m = cur + 1; m < next_s; ++m)
        ((float4*)(out + (size_t)m * FEAT))[lane] = bia;
}

// K2: finalize boundary-crossing segments. One 16-lane group per K1 group.
__global__ void __launch_bounds__(THREADS)
fixup_kernel(const int* __restrict__ seg,
             float* __restrict__ out,
             const float4* __restrict__ bias4,
             int n_groups) {
    int row  = blockIdx.x * ROWS_PER_BLOCK + (threadIdx.x >> 4);
    int lane = threadIdx.x & 15;
    if (row >= n_groups) return;

    unsigned char flag = g_flags[row];
    if (!(flag & FLG_OWNED_TAIL)) return;

    int t = g_tail_id[row];
    float4 bia = __ldg(&bias4[lane]);
    float4 s = g_scratch_tail[(size_t)row * 16 + lane];
    float4 sum = make_float4(s.x + bia.x, s.y + bia.y, s.z + bia.z, s.w + bia.w);

    for (int g = row + 1; g < n_groups; ++g) {
        if (__ldg(&seg[g * EPR]) != t) break;   // continuation groups only
        float4 h = g_scratch_head[(size_t)g * 16 + lane];
        sum.x += h.x; sum.y += h.y; sum.z += h.z; sum.w += h.w;
        if (!(g_flags[g] & FLG_FULL)) break;    // segment ended inside g
    }
    ((float4*)(out + (size_t)t * FEAT))[lane] = sum;
}

extern "C" void kernel_launch(void* const* d_in, const int* in_sizes, int n_in,
                              void* d_out, int out_size) {
    // metadata order: nodes[0] (unused), neighbor_feats[1], attention[2],
    //                 bias[3], segment_ids[4]
    const float* feats = (const float*)d_in[1];
    const float* attn  = (const float*)d_in[2];
    const float* bias  = (const float*)d_in[3];
    const int*   seg   = (const int*)d_in[4];
    float* out = (float*)d_out;

    int n_edges = in_sizes[2];          // attention element count = E
    int n_nodes = out_size / FEAT;      // N

    int n_groups = (n_edges + EPR - 1) / EPR;
    int blocks1  = (n_groups + ROWS_PER_BLOCK - 1) / ROWS_PER_BLOCK;
    segsum_kernel<<<blocks1, THREADS>>>((const float4*)feats, attn, seg, out,
                                        (const float4*)bias, n_edges, n_nodes);

    int blocks2 = (n_groups + ROWS_PER_BLOCK - 1) / ROWS_PER_BLOCK;
    fixup_kernel<<<blocks2, THREADS>>>(seg, out, (const float4*)bias, n_groups);
}